// round 16
// baseline (speedup 1.0000x reference)
#include <cuda_runtime.h>
#include <cuda_fp16.h>
#include <cstdint>

// Problem constants
#define B_   2
#define S_   2048
#define D_   1024
#define H_   16
#define DH_  64
#define M_   4096      /* B_*S_ rows */

// Q scale: 1/sqrt(64) * log2(e)  (log2e folded so softmax uses pure 2^x)
#define QSCALE 0.1803368801111204f

// Scratch (static device globals — no runtime allocation)
__device__ __half g_xh  [M_ * D_];
__device__ __half g_wh  [3 * D_ * D_];
__device__ __half g_woth[D_ * D_];
__device__ __half g_qh  [M_ * D_];
__device__ __half g_kh  [M_ * D_];
__device__ __half g_vh  [M_ * D_];
__device__ __half g_zh  [M_ * D_];

// ---------------------------------------------------------------------------
// small helpers
// ---------------------------------------------------------------------------
__device__ __forceinline__ float ex2f(float x)
{
    float y;
    asm("ex2.approx.f32 %0, %1;" : "=f"(y) : "f"(x));
    return y;
}
__device__ __forceinline__ uint32_t h2ex2(uint32_t x)
{
    uint32_t d;
    asm("ex2.approx.f16x2 %0, %1;" : "=r"(d) : "r"(x));
    return d;
}
__device__ __forceinline__ void mma16816(float c[4], const uint32_t a[4],
                                         uint32_t b0, uint32_t b1)
{
    asm volatile(
        "mma.sync.aligned.m16n8k16.row.col.f32.f16.f16.f32 "
        "{%0,%1,%2,%3},{%4,%5,%6,%7},{%8,%9},{%0,%1,%2,%3};"
        : "+f"(c[0]), "+f"(c[1]), "+f"(c[2]), "+f"(c[3])
        : "r"(a[0]), "r"(a[1]), "r"(a[2]), "r"(a[3]), "r"(b0), "r"(b1));
}
// fp16-accumulate variant (C/D packed f16x2)
__device__ __forceinline__ void mma16816h(uint32_t c[2], const uint32_t a[4],
                                          uint32_t b0, uint32_t b1)
{
    asm volatile(
        "mma.sync.aligned.m16n8k16.row.col.f16.f16.f16.f16 "
        "{%0,%1},{%2,%3,%4,%5},{%6,%7},{%0,%1};"
        : "+r"(c[0]), "+r"(c[1])
        : "r"(a[0]), "r"(a[1]), "r"(a[2]), "r"(a[3]), "r"(b0), "r"(b1));
}
__device__ __forceinline__ void ldsm4(uint32_t r[4], uint32_t addr)
{
    asm volatile("ldmatrix.sync.aligned.m8n8.x4.shared.b16 {%0,%1,%2,%3}, [%4];"
                 : "=r"(r[0]), "=r"(r[1]), "=r"(r[2]), "=r"(r[3]) : "r"(addr));
}
__device__ __forceinline__ void ldsm4t(uint32_t r[4], uint32_t addr)
{
    asm volatile("ldmatrix.sync.aligned.m8n8.x4.trans.shared.b16 {%0,%1,%2,%3}, [%4];"
                 : "=r"(r[0]), "=r"(r[1]), "=r"(r[2]), "=r"(r[3]) : "r"(addr));
}

// ---------------------------------------------------------------------------
// prep: pack x -> half, pack W_QKV -> half.  MLP=4 (4 independent float4s
// per thread).  Grid: [0,1024) x | [1024,1792) W_QKV
// ---------------------------------------------------------------------------
__global__ void __launch_bounds__(256)
prep_kernel(const float* __restrict__ x,
            const float* __restrict__ wq, const float* __restrict__ wk,
            const float* __restrict__ wv)
{
    const int blk = blockIdx.x;
    const float* src;
    __half* dst;
    int i0;
    if (blk < 1024) {                       // x: 1M float4
        src = x;
        dst = g_xh;
        i0 = blk * 1024 + threadIdx.x;
    } else {                                // W: 3 x 256K float4
        const int blkw = blk - 1024;        // 0..767
        const int z    = blkw >> 8;
        src = (z == 0) ? wq : (z == 1) ? wk : wv;
        dst = g_wh + (size_t)z * 1048576;
        i0 = (blkw & 255) * 1024 + threadIdx.x;
    }
    float4 v[4];
#pragma unroll
    for (int m = 0; m < 4; ++m)
        v[m] = ((const float4*)src)[i0 + m * 256];
#pragma unroll
    for (int m = 0; m < 4; ++m) {
        const int i = i0 + m * 256;
        ((__half2*)dst)[2 * i]     = __floats2half2_rn(v[m].x, v[m].y);
        ((__half2*)dst)[2 * i + 1] = __floats2half2_rn(v[m].z, v[m].w);
    }
}

// W_O [H, D, DH] -> g_woth[d][i*64+h] (half), MLP=4 — off the critical path
__global__ void __launch_bounds__(256)
prep_wo_kernel(const float* __restrict__ wo)
{
    const int idx0 = blockIdx.x * 1024 + threadIdx.x;
    float v[4];
#pragma unroll
    for (int m = 0; m < 4; ++m) {
        const int idx = idx0 + m * 256;
        const int h = idx & 63;
        const int i = (idx >> 6) & 15;
        const int d = idx >> 10;
        v[m] = wo[((size_t)i * 1024 + d) * 64 + h];
    }
#pragma unroll
    for (int m = 0; m < 4; ++m)
        g_woth[idx0 + m * 256] = __float2half(v[m]);
}

// ---------------------------------------------------------------------------
// FP16 tensor GEMM: C = A[4096,1024] * W[1024,1024]^T + bias
// Block tile 256x128, BK=64, 8 warps (4 row x 2 col), warp tile 64x64,
// mma m16n8k16, cp.async double buffer, SW128 swizzle. yoff splits batches.
// ---------------------------------------------------------------------------
#define HG_SMEM (1024 + 2 * 49152)   /* bias + 2 x (A 32KB + B 16KB) */

__device__ __forceinline__ void hstage(const __half* __restrict__ A,
                                       const __half* __restrict__ W,
                                       int rowBase, int colBase, int kt,
                                       uint32_t sdst, int tid)
{
#pragma unroll
    for (int i = 0; i < 12; ++i) {
        const int cid = tid + i * 256;          // 0..3071
        const int isA = (cid < 2048);
        const int row = isA ? (cid >> 3) : ((cid - 2048) >> 3);
        const int kc  = cid & 7;
        const __half* src = (isA
            ? A + (size_t)(rowBase + row) * 1024
            : W + (size_t)(colBase + row) * 1024) + kt * 64 + kc * 8;
        const uint32_t dst = sdst + (isA ? 0 : 32768)
                           + (row << 7) + ((kc ^ (row & 7)) << 4);
        asm volatile("cp.async.cg.shared.global [%0], [%1], 16;\n" :: "r"(dst), "l"(src));
    }
}

template <int OUT_HALF>
__device__ __forceinline__ void hgemm256(const __half* __restrict__ A,
                                         const __half* __restrict__ W,
                                         const float* __restrict__ bias,
                                         void* __restrict__ Cout,
                                         float oscale, char* sm, int yoff)
{
    float* const biasSm = (float*)sm;
    const uint32_t sBuf = (uint32_t)__cvta_generic_to_shared(sm) + 1024;

    const int tid  = threadIdx.x;
    const int lane = tid & 31;
    const int w    = tid >> 5;
    const int wr   = w & 3;       // 4 x 64-row groups
    const int wc   = w >> 2;      // 2 x 64-col groups
    const int rowBase = (blockIdx.y + yoff) * 256;
    const int colBase = blockIdx.x * 128;

    float acc[4][8][4] = {};

    const int lane7 = lane & 7;
    const int rA    = wr * 64 + (lane & 15);
    const int cA    = lane >> 4;
    const int rB    = wc * 64 + ((lane >> 4) << 3) + lane7;  // + p*16
    const int bPar  = (lane >> 3) & 1;

    if (tid < 128) biasSm[tid] = bias[colBase + tid];

    hstage(A, W, rowBase, colBase, 0, sBuf, tid);
    asm volatile("cp.async.commit_group;\n");

    for (int kt = 0; kt < 16; ++kt) {
        __syncthreads();
        if (kt + 1 < 16)
            hstage(A, W, rowBase, colBase, kt + 1, sBuf + ((kt + 1) & 1) * 49152, tid);
        asm volatile("cp.async.commit_group;\n");
        asm volatile("cp.async.wait_group 1;\n");
        __syncthreads();

        const uint32_t aBase = sBuf + (kt & 1) * 49152;
        const uint32_t bBase = aBase + 32768;
#pragma unroll
        for (int kk = 0; kk < 4; ++kk) {
            uint32_t a[4][4], b[8][2];
#pragma unroll
            for (int mt = 0; mt < 4; ++mt) {
                const int row = rA + mt * 16;
                const uint32_t addr = aBase + (row << 7)
                    + ((((kk << 1) + cA) ^ (row & 7)) << 4);
                ldsm4(a[mt], addr);
            }
#pragma unroll
            for (int p = 0; p < 4; ++p) {
                const int row = rB + p * 16;
                const uint32_t addr = bBase + (row << 7)
                    + ((((kk << 1) + bPar) ^ lane7) << 4);
                uint32_t t[4];
                ldsm4(t, addr);
                b[2 * p][0] = t[0]; b[2 * p][1] = t[1];
                b[2 * p + 1][0] = t[2]; b[2 * p + 1][1] = t[3];
            }
#pragma unroll
            for (int mt = 0; mt < 4; ++mt)
#pragma unroll
                for (int nt = 0; nt < 8; ++nt)
                    mma16816(acc[mt][nt], a[mt], b[nt][0], b[nt][1]);
        }
    }

    // Epilogue
#pragma unroll
    for (int mt = 0; mt < 4; ++mt) {
        const int r0 = rowBase + wr * 64 + mt * 16 + (lane >> 2);
#pragma unroll
        for (int half_ = 0; half_ < 2; ++half_) {
            const int r = r0 + half_ * 8;
#pragma unroll
            for (int nt = 0; nt < 8; ++nt) {
                const int cl = wc * 64 + nt * 8 + 2 * (lane & 3);
                const int c  = colBase + cl;
                const float v0 = (acc[mt][nt][half_ * 2 + 0] + biasSm[cl])     * oscale;
                const float v1 = (acc[mt][nt][half_ * 2 + 1] + biasSm[cl + 1]) * oscale;
                if (OUT_HALF) {
                    *(__half2*)((__half*)Cout + (size_t)r * 1024 + c) =
                        __floats2half2_rn(v0, v1);
                } else {
                    *(float2*)((float*)Cout + (size_t)r * 1024 + c) =
                        make_float2(v0, v1);
                }
            }
        }
    }
}

// QKV projection: blockIdx.z selects Q/K/V (q scaled by QSCALE)
__global__ void __launch_bounds__(256, 1)
qkv_kernel(const float* __restrict__ bq, const float* __restrict__ bk,
           const float* __restrict__ bv, int yoff)
{
    extern __shared__ char smc[];
    const int z = blockIdx.z;
    const __half* W = g_wh + (size_t)z * 1048576;
    const float* b  = (z == 0) ? bq : (z == 1) ? bk : bv;
    __half* O       = (z == 0) ? g_qh : (z == 1) ? g_kh : g_vh;
    const float sc  = (z == 0) ? QSCALE : 1.f;
    hgemm256<1>(g_xh, W, b, O, sc, smc, yoff);
}

// Output projection: out = z @ WoT^T + b_O (float out)
__global__ void __launch_bounds__(256, 1)
out_kernel(const float* __restrict__ bo, float* __restrict__ out, int yoff)
{
    extern __shared__ char smc[];
    hgemm256<0>(g_zh, g_woth, bo, out, 1.f, smc, yoff);
}

// ---------------------------------------------------------------------------
// FP16 tensor-core flash attention, BKEY=128 (empirical optimum: fp16 S
// accumulators, staged fragment arrays for ILP, branch-free mainloop,
// 1 CTA/SM).
// ---------------------------------------------------------------------------
#define FL_SMEM (16384 + 32768 + 32768)   /* Q + K(2x16K) + V(2x16K) = 80KB */

__global__ void __launch_bounds__(256, 1)
flash_kernel(int bb)
{
    extern __shared__ __align__(16) char smc[];
    const uint32_t sQ = (uint32_t)__cvta_generic_to_shared(smc);
    const uint32_t sK = sQ + 16384;
    const uint32_t sV = sK + 32768;

    const int qt  = 15 - blockIdx.x;  // heavy CTAs first
    const int h   = blockIdx.y;
    const int tid = threadIdx.x;
    const int lane = tid & 31;
    const int wid  = tid >> 5;
    const int lane7 = lane & 7;

    const int qbase = qt * 128;
    const int wrow  = wid * 16;
    const size_t base = (size_t)bb * S_ * 1024 + (size_t)h * 64;
    const __half* const Qg = g_qh + base;
    const __half* const Kg = g_kh + base;
    const __half* const Vg = g_vh + base;

    // ---- stage Q (128 rows) ----
#pragma unroll
    for (int i = 0; i < 4; ++i) {
        const int cid = tid + i * 256;          // 0..1023
        const int row = cid >> 3;
        const int kc  = cid & 7;
        const __half* src = Qg + (size_t)(qbase + row) * 1024 + kc * 8;
        const uint32_t dst = sQ + (row << 7) + ((kc ^ (row & 7)) << 4);
        asm volatile("cp.async.cg.shared.global [%0], [%1], 16;\n" :: "r"(dst), "l"(src));
    }
    // ---- stage K/V tile 0 (128 keys) ----
#pragma unroll
    for (int i = 0; i < 8; ++i) {
        const int cid = tid + i * 256;          // 0..2047 : 1024 K, 1024 V
        const int row = (cid >> 3) & 127;
        const int kc  = cid & 7;
        const __half* src = ((cid < 1024) ? Kg : Vg) + (size_t)row * 1024 + kc * 8;
        const uint32_t dst = ((cid < 1024) ? sK : sV)
                           + (row << 7) + ((kc ^ (row & 7)) << 4);
        asm volatile("cp.async.cg.shared.global [%0], [%1], 16;\n" :: "r"(dst), "l"(src));
    }
    asm volatile("cp.async.commit_group;\n");

    // per-thread ldmatrix selectors
    const int qRow    = wrow + (lane & 15);
    const int qCsel   = lane >> 4;
    const int kRowSel = ((lane >> 4) << 3) + lane7;   // + p*16
    const int kPar    = (lane >> 3) & 1;
    const int vRow    = lane & 15;                    // + kt16*16
    const int vCsel   = lane >> 4;                    // + 2*p

    uint32_t qa[4][4];
    float oacc[8][4] = {};
    float l0 = 0.f, l1 = 0.f;
    float mrow0 = -1e30f, mrow1 = -1e30f;

    const int ntile = qt + 1;
    for (int kt = 0; kt < ntile; ++kt) {
        __syncthreads();  // buffer-reuse guard
        if (kt + 1 < ntile) {
            const int kb2 = (kt + 1) * 128;
            const uint32_t boff = ((kt + 1) & 1) * 16384;
#pragma unroll
            for (int i = 0; i < 8; ++i) {
                const int cid = tid + i * 256;
                const int row = (cid >> 3) & 127;
                const int kc  = cid & 7;
                const __half* src = ((cid < 1024) ? Kg : Vg)
                                  + (size_t)(kb2 + row) * 1024 + kc * 8;
                const uint32_t dst = ((cid < 1024) ? sK : sV) + boff
                                   + (row << 7) + ((kc ^ (row & 7)) << 4);
                asm volatile("cp.async.cg.shared.global [%0], [%1], 16;\n" :: "r"(dst), "l"(src));
            }
        }
        asm volatile("cp.async.commit_group;\n");
        asm volatile("cp.async.wait_group 1;\n");
        __syncthreads();

        if (kt == 0) {   // extract Q fragments once (group 0 complete)
#pragma unroll
            for (int kk = 0; kk < 4; ++kk) {
                const uint32_t addr = sQ + (qRow << 7)
                    + ((((kk << 1) + qCsel) ^ (qRow & 7)) << 4);
                ldsm4(qa[kk], addr);
            }
        }

        const uint32_t Kbuf = sK + (kt & 1) * 16384;
        const uint32_t Vbuf = sV + (kt & 1) * 16384;
        const int kbase = kt * 128;

        // ---- S = Q K^T (fp16 accumulators; 16 n-tiles of 8 keys) ----
        uint32_t sacc[16][2] = {};
#pragma unroll
        for (int kk = 0; kk < 4; ++kk) {
            uint32_t bk[16][2];
#pragma unroll
            for (int p = 0; p < 8; ++p) {
                const int row = p * 16 + kRowSel;
                const uint32_t addr = Kbuf + (row << 7)
                    + ((((kk << 1) + kPar) ^ lane7) << 4);
                uint32_t t[4];
                ldsm4(t, addr);
                bk[2 * p][0] = t[0]; bk[2 * p][1] = t[1];
                bk[2 * p + 1][0] = t[2]; bk[2 * p + 1][1] = t[3];
            }
#pragma unroll
            for (int nt = 0; nt < 16; ++nt)
                mma16816h(sacc[nt], qa[kk], bk[nt][0], bk[nt][1]);
        }

        // ---- causal mask (diagonal tile only: kt == qt); -65504h = 0xFBFF ----
        if (kt == qt) {
            const int r0g = qbase + wrow + (lane >> 2);
#pragma unroll
            for (int nt = 0; nt < 16; ++nt) {
                const int cg = kbase + nt * 8 + 2 * (lane & 3);
                {
                    uint32_t s = sacc[nt][0];
                    if (cg + 1 > r0g) s = (s & 0x0000FFFFu) | 0xFBFF0000u;
                    if (cg     > r0g) s = (s & 0xFFFF0000u) | 0x0000FBFFu;
                    sacc[nt][0] = s;
                }
                {
                    uint32_t s = sacc[nt][1];
                    if (cg + 1 > r0g + 8) s = (s & 0x0000FFFFu) | 0xFBFF0000u;
                    if (cg     > r0g + 8) s = (s & 0xFFFF0000u) | 0x0000FBFFu;
                    sacc[nt][1] = s;
                }
            }
        }

        // ---- online softmax (fp16 max chain; maxes fp16-exact) ----
        __half2 hm0 = *(const __half2*)&sacc[0][0];
        __half2 hm1 = *(const __half2*)&sacc[0][1];
#pragma unroll
        for (int nt = 1; nt < 16; ++nt) {
            hm0 = __hmax2(hm0, *(const __half2*)&sacc[nt][0]);
            hm1 = __hmax2(hm1, *(const __half2*)&sacc[nt][1]);
        }
        const float2 fm0 = __half22float2(hm0);
        const float2 fm1 = __half22float2(hm1);
        float mx0 = fmaxf(fm0.x, fm0.y);
        float mx1 = fmaxf(fm1.x, fm1.y);
        mx0 = fmaxf(mx0, __shfl_xor_sync(0xffffffffu, mx0, 1));
        mx0 = fmaxf(mx0, __shfl_xor_sync(0xffffffffu, mx0, 2));
        mx1 = fmaxf(mx1, __shfl_xor_sync(0xffffffffu, mx1, 1));
        mx1 = fmaxf(mx1, __shfl_xor_sync(0xffffffffu, mx1, 2));

        const float mn0 = fmaxf(mrow0, mx0);
        const float mn1 = fmaxf(mrow1, mx1);
        const float alpha0 = ex2f(mrow0 - mn0);
        const float alpha1 = ex2f(mrow1 - mn1);
        mrow0 = mn0; mrow1 = mn1;

        const __half2 mh0 = __float2half2_rn(mn0);   // exact
        const __half2 mh1 = __float2half2_rn(mn1);

        uint32_t ph[16][2];
#pragma unroll
        for (int nt = 0; nt < 16; ++nt) {
            const __half2 d0 = __hsub2(*(const __half2*)&sacc[nt][0], mh0);
            const __half2 d1 = __hsub2(*(const __half2*)&sacc[nt][1], mh1);
            ph[nt][0] = h2ex2(*(const uint32_t*)&d0);
            ph[nt][1] = h2ex2(*(const uint32_t*)&d1);
        }

        // ---- row sums on fma/alu pipes ----
        float rs0 = 0.f, rs1 = 0.f;
#pragma unroll
        for (int nt = 0; nt < 16; nt += 2) {
            const __half2 a0 = __hadd2(*(const __half2*)&ph[nt][0],
                                       *(const __half2*)&ph[nt + 1][0]);
            const __half2 a1 = __hadd2(*(const __half2*)&ph[nt][1],
                                       *(const __half2*)&ph[nt + 1][1]);
            const float2 f0 = __half22float2(a0);
            const float2 f1 = __half22float2(a1);
            rs0 += f0.x + f0.y;
            rs1 += f1.x + f1.y;
        }
        rs0 += __shfl_xor_sync(0xffffffffu, rs0, 1);
        rs0 += __shfl_xor_sync(0xffffffffu, rs0, 2);
        rs1 += __shfl_xor_sync(0xffffffffu, rs1, 1);
        rs1 += __shfl_xor_sync(0xffffffffu, rs1, 2);
        l0 = l0 * alpha0 + rs0;
        l1 = l1 * alpha1 + rs1;

#pragma unroll
        for (int nt = 0; nt < 8; ++nt) {
            oacc[nt][0] *= alpha0; oacc[nt][1] *= alpha0;
            oacc[nt][2] *= alpha1; oacc[nt][3] *= alpha1;
        }

        // ---- O += P V (fp32 accumulators) ----
#pragma unroll
        for (int kt16 = 0; kt16 < 8; ++kt16) {
            uint32_t pa[4];
            pa[0] = ph[2 * kt16][0];
            pa[1] = ph[2 * kt16][1];
            pa[2] = ph[2 * kt16 + 1][0];
            pa[3] = ph[2 * kt16 + 1][1];

            uint32_t bv[8][2];
#pragma unroll
            for (int p = 0; p < 4; ++p) {
                const int row = kt16 * 16 + vRow;
                const uint32_t addr = Vbuf + (row << 7)
                    + ((((p << 1) + vCsel) ^ (row & 7)) << 4);
                uint32_t t[4];
                ldsm4t(t, addr);
                bv[2 * p][0] = t[0]; bv[2 * p][1] = t[1];
                bv[2 * p + 1][0] = t[2]; bv[2 * p + 1][1] = t[3];
            }
#pragma unroll
            for (int nt = 0; nt < 8; ++nt)
                mma16816(oacc[nt], pa, bv[nt][0], bv[nt][1]);
        }
    }

    // ---- normalize + write z (half) ----
    const float inv0 = 1.f / l0;
    const float inv1 = 1.f / l1;
    __half* const Zg = g_zh + base;
    const int r0 = qbase + wrow + (lane >> 2);
#pragma unroll
    for (int nt = 0; nt < 8; ++nt) {
        const int c = nt * 8 + 2 * (lane & 3);
        *(__half2*)(Zg + (size_t)r0 * 1024 + c) =
            __floats2half2_rn(oacc[nt][0] * inv0, oacc[nt][1] * inv0);
        *(__half2*)(Zg + (size_t)(r0 + 8) * 1024 + c) =
            __floats2half2_rn(oacc[nt][2] * inv1, oacc[nt][3] * inv1);
    }
}

// ---------------------------------------------------------------------------
extern "C" void kernel_launch(void* const* d_in, const int* in_sizes, int n_in,
                              void* d_out, int out_size)
{
    (void)in_sizes; (void)n_in; (void)out_size;
    const float* x  = (const float*)d_in[0];
    const float* Wq = (const float*)d_in[1];
    const float* Wk = (const float*)d_in[2];
    const float* Wv = (const float*)d_in[3];
    const float* Wo = (const float*)d_in[4];
    const float* bq = (const float*)d_in[5];
    const float* bk = (const float*)d_in[6];
    const float* bv = (const float*)d_in[7];
    const float* bo = (const float*)d_in[8];
    float* out = (float*)d_out;

    cudaFuncSetAttribute(flash_kernel,
                         cudaFuncAttributeMaxDynamicSharedMemorySize, FL_SMEM);
    cudaFuncSetAttribute(qkv_kernel,
                         cudaFuncAttributeMaxDynamicSharedMemorySize, HG_SMEM);
    cudaFuncSetAttribute(out_kernel,
                         cudaFuncAttributeMaxDynamicSharedMemorySize, HG_SMEM);

    cudaStream_t s1, s2;
    cudaStreamCreateWithFlags(&s1, cudaStreamNonBlocking);
    cudaStreamCreateWithFlags(&s2, cudaStreamNonBlocking);
    cudaEvent_t evFork, evPrep, evWO, evJoin;
    cudaEventCreateWithFlags(&evFork, cudaEventDisableTiming);
    cudaEventCreateWithFlags(&evPrep, cudaEventDisableTiming);
    cudaEventCreateWithFlags(&evWO,   cudaEventDisableTiming);
    cudaEventCreateWithFlags(&evJoin, cudaEventDisableTiming);

    // fork s2 for the W_O transpose (only needed by the out_kernels)
    cudaEventRecord(evFork, 0);
    cudaStreamWaitEvent(s2, evFork, 0);
    prep_wo_kernel<<<1024, 256, 0, s2>>>(Wo);
    cudaEventRecord(evWO, s2);

    // critical-path prep (x + W_QKV), then fork s1 for batch 1
    prep_kernel<<<1792, 256>>>(x, Wq, Wk, Wv);
    cudaEventRecord(evPrep, 0);
    cudaStreamWaitEvent(s1, evPrep, 0);

    // chain 0 (rows 0..2047 = batch 0) on the default stream
    qkv_kernel<<<dim3(8, 8, 3), 256, HG_SMEM>>>(bq, bk, bv, 0);
    flash_kernel<<<dim3(16, 16), 256, FL_SMEM>>>(0);
    cudaStreamWaitEvent(0, evWO, 0);
    out_kernel<<<dim3(8, 8), 256, HG_SMEM>>>(bo, out, 0);

    // chain 1 (rows 2048..4095 = batch 1) on s1
    qkv_kernel<<<dim3(8, 8, 3), 256, HG_SMEM, s1>>>(bq, bk, bv, 8);
    flash_kernel<<<dim3(16, 16), 256, FL_SMEM, s1>>>(1);
    cudaStreamWaitEvent(s1, evWO, 0);
    out_kernel<<<dim3(8, 8), 256, HG_SMEM, s1>>>(bo, out, 8);

    cudaEventRecord(evJoin, s1);
    cudaStreamWaitEvent(0, evJoin, 0);

    cudaEventDestroy(evFork);
    cudaEventDestroy(evPrep);
    cudaEventDestroy(evWO);
    cudaEventDestroy(evJoin);
    cudaStreamDestroy(s1);
    cudaStreamDestroy(s2);
}

// round 17
// speedup vs baseline: 1.0107x; 1.0107x over previous
#include <cuda_runtime.h>
#include <cuda_fp16.h>
#include <cstdint>

// Problem constants
#define B_   2
#define S_   2048
#define D_   1024
#define H_   16
#define DH_  64
#define M_   4096      /* B_*S_ rows */

// Q scale: 1/sqrt(64) * log2(e)  (log2e folded so softmax uses pure 2^x)
#define QSCALE 0.1803368801111204f

// Scratch (static device globals — no runtime allocation)
__device__ __half g_xh  [M_ * D_];
__device__ __half g_wh  [3 * D_ * D_];
__device__ __half g_woth[D_ * D_];
__device__ __half g_qh  [M_ * D_];
__device__ __half g_kh  [M_ * D_];
__device__ __half g_vh  [M_ * D_];
__device__ __half g_zh  [M_ * D_];

// ---------------------------------------------------------------------------
// small helpers
// ---------------------------------------------------------------------------
__device__ __forceinline__ float ex2f(float x)
{
    float y;
    asm("ex2.approx.f32 %0, %1;" : "=f"(y) : "f"(x));
    return y;
}
__device__ __forceinline__ uint32_t h2ex2(uint32_t x)
{
    uint32_t d;
    asm("ex2.approx.f16x2 %0, %1;" : "=r"(d) : "r"(x));
    return d;
}
__device__ __forceinline__ void mma16816(float c[4], const uint32_t a[4],
                                         uint32_t b0, uint32_t b1)
{
    asm volatile(
        "mma.sync.aligned.m16n8k16.row.col.f32.f16.f16.f32 "
        "{%0,%1,%2,%3},{%4,%5,%6,%7},{%8,%9},{%0,%1,%2,%3};"
        : "+f"(c[0]), "+f"(c[1]), "+f"(c[2]), "+f"(c[3])
        : "r"(a[0]), "r"(a[1]), "r"(a[2]), "r"(a[3]), "r"(b0), "r"(b1));
}
// fp16-accumulate variant (C/D packed f16x2)
__device__ __forceinline__ void mma16816h(uint32_t c[2], const uint32_t a[4],
                                          uint32_t b0, uint32_t b1)
{
    asm volatile(
        "mma.sync.aligned.m16n8k16.row.col.f16.f16.f16.f16 "
        "{%0,%1},{%2,%3,%4,%5},{%6,%7},{%0,%1};"
        : "+r"(c[0]), "+r"(c[1])
        : "r"(a[0]), "r"(a[1]), "r"(a[2]), "r"(a[3]), "r"(b0), "r"(b1));
}
__device__ __forceinline__ void ldsm4(uint32_t r[4], uint32_t addr)
{
    asm volatile("ldmatrix.sync.aligned.m8n8.x4.shared.b16 {%0,%1,%2,%3}, [%4];"
                 : "=r"(r[0]), "=r"(r[1]), "=r"(r[2]), "=r"(r[3]) : "r"(addr));
}
__device__ __forceinline__ void ldsm4t(uint32_t r[4], uint32_t addr)
{
    asm volatile("ldmatrix.sync.aligned.m8n8.x4.trans.shared.b16 {%0,%1,%2,%3}, [%4];"
                 : "=r"(r[0]), "=r"(r[1]), "=r"(r[2]), "=r"(r[3]) : "r"(addr));
}

// ---------------------------------------------------------------------------
// prep: pack x -> half, pack W_QKV -> half.  MLP=4 (4 independent float4s
// per thread).  Grid: [0,1024) x | [1024,1792) W_QKV
// ---------------------------------------------------------------------------
__global__ void __launch_bounds__(256)
prep_kernel(const float* __restrict__ x,
            const float* __restrict__ wq, const float* __restrict__ wk,
            const float* __restrict__ wv)
{
    const int blk = blockIdx.x;
    const float* src;
    __half* dst;
    int i0;
    if (blk < 1024) {                       // x: 1M float4
        src = x;
        dst = g_xh;
        i0 = blk * 1024 + threadIdx.x;
    } else {                                // W: 3 x 256K float4
        const int blkw = blk - 1024;        // 0..767
        const int z    = blkw >> 8;
        src = (z == 0) ? wq : (z == 1) ? wk : wv;
        dst = g_wh + (size_t)z * 1048576;
        i0 = (blkw & 255) * 1024 + threadIdx.x;
    }
    float4 v[4];
#pragma unroll
    for (int m = 0; m < 4; ++m)
        v[m] = ((const float4*)src)[i0 + m * 256];
#pragma unroll
    for (int m = 0; m < 4; ++m) {
        const int i = i0 + m * 256;
        ((__half2*)dst)[2 * i]     = __floats2half2_rn(v[m].x, v[m].y);
        ((__half2*)dst)[2 * i + 1] = __floats2half2_rn(v[m].z, v[m].w);
    }
}

// W_O [H, D, DH] -> g_woth[d][i*64+h] (half), MLP=4 — off the critical path
__global__ void __launch_bounds__(256)
prep_wo_kernel(const float* __restrict__ wo)
{
    const int idx0 = blockIdx.x * 1024 + threadIdx.x;
    float v[4];
#pragma unroll
    for (int m = 0; m < 4; ++m) {
        const int idx = idx0 + m * 256;
        const int h = idx & 63;
        const int i = (idx >> 6) & 15;
        const int d = idx >> 10;
        v[m] = wo[((size_t)i * 1024 + d) * 64 + h];
    }
#pragma unroll
    for (int m = 0; m < 4; ++m)
        g_woth[idx0 + m * 256] = __float2half(v[m]);
}

// ---------------------------------------------------------------------------
// FP16 tensor GEMM: C = A[4096,1024] * W[1024,1024]^T + bias
// Block tile 256x128, BK=64, 8 warps (4 row x 2 col), warp tile 64x64,
// mma m16n8k16, cp.async double buffer, SW128 swizzle. yoff splits batches.
// ---------------------------------------------------------------------------
#define HG_SMEM (1024 + 2 * 49152)   /* bias + 2 x (A 32KB + B 16KB) */

__device__ __forceinline__ void hstage(const __half* __restrict__ A,
                                       const __half* __restrict__ W,
                                       int rowBase, int colBase, int kt,
                                       uint32_t sdst, int tid)
{
#pragma unroll
    for (int i = 0; i < 12; ++i) {
        const int cid = tid + i * 256;          // 0..3071
        const int isA = (cid < 2048);
        const int row = isA ? (cid >> 3) : ((cid - 2048) >> 3);
        const int kc  = cid & 7;
        const __half* src = (isA
            ? A + (size_t)(rowBase + row) * 1024
            : W + (size_t)(colBase + row) * 1024) + kt * 64 + kc * 8;
        const uint32_t dst = sdst + (isA ? 0 : 32768)
                           + (row << 7) + ((kc ^ (row & 7)) << 4);
        asm volatile("cp.async.cg.shared.global [%0], [%1], 16;\n" :: "r"(dst), "l"(src));
    }
}

template <int OUT_HALF>
__device__ __forceinline__ void hgemm256(const __half* __restrict__ A,
                                         const __half* __restrict__ W,
                                         const float* __restrict__ bias,
                                         void* __restrict__ Cout,
                                         float oscale, char* sm, int yoff)
{
    float* const biasSm = (float*)sm;
    const uint32_t sBuf = (uint32_t)__cvta_generic_to_shared(sm) + 1024;

    const int tid  = threadIdx.x;
    const int lane = tid & 31;
    const int w    = tid >> 5;
    const int wr   = w & 3;       // 4 x 64-row groups
    const int wc   = w >> 2;      // 2 x 64-col groups
    const int rowBase = (blockIdx.y + yoff) * 256;
    const int colBase = blockIdx.x * 128;

    float acc[4][8][4] = {};

    const int lane7 = lane & 7;
    const int rA    = wr * 64 + (lane & 15);
    const int cA    = lane >> 4;
    const int rB    = wc * 64 + ((lane >> 4) << 3) + lane7;  // + p*16
    const int bPar  = (lane >> 3) & 1;

    if (tid < 128) biasSm[tid] = bias[colBase + tid];

    hstage(A, W, rowBase, colBase, 0, sBuf, tid);
    asm volatile("cp.async.commit_group;\n");

    for (int kt = 0; kt < 16; ++kt) {
        __syncthreads();
        if (kt + 1 < 16)
            hstage(A, W, rowBase, colBase, kt + 1, sBuf + ((kt + 1) & 1) * 49152, tid);
        asm volatile("cp.async.commit_group;\n");
        asm volatile("cp.async.wait_group 1;\n");
        __syncthreads();

        const uint32_t aBase = sBuf + (kt & 1) * 49152;
        const uint32_t bBase = aBase + 32768;
#pragma unroll
        for (int kk = 0; kk < 4; ++kk) {
            uint32_t a[4][4], b[8][2];
#pragma unroll
            for (int mt = 0; mt < 4; ++mt) {
                const int row = rA + mt * 16;
                const uint32_t addr = aBase + (row << 7)
                    + ((((kk << 1) + cA) ^ (row & 7)) << 4);
                ldsm4(a[mt], addr);
            }
#pragma unroll
            for (int p = 0; p < 4; ++p) {
                const int row = rB + p * 16;
                const uint32_t addr = bBase + (row << 7)
                    + ((((kk << 1) + bPar) ^ lane7) << 4);
                uint32_t t[4];
                ldsm4(t, addr);
                b[2 * p][0] = t[0]; b[2 * p][1] = t[1];
                b[2 * p + 1][0] = t[2]; b[2 * p + 1][1] = t[3];
            }
#pragma unroll
            for (int mt = 0; mt < 4; ++mt)
#pragma unroll
                for (int nt = 0; nt < 8; ++nt)
                    mma16816(acc[mt][nt], a[mt], b[nt][0], b[nt][1]);
        }
    }

    // Epilogue
#pragma unroll
    for (int mt = 0; mt < 4; ++mt) {
        const int r0 = rowBase + wr * 64 + mt * 16 + (lane >> 2);
#pragma unroll
        for (int half_ = 0; half_ < 2; ++half_) {
            const int r = r0 + half_ * 8;
#pragma unroll
            for (int nt = 0; nt < 8; ++nt) {
                const int cl = wc * 64 + nt * 8 + 2 * (lane & 3);
                const int c  = colBase + cl;
                const float v0 = (acc[mt][nt][half_ * 2 + 0] + biasSm[cl])     * oscale;
                const float v1 = (acc[mt][nt][half_ * 2 + 1] + biasSm[cl + 1]) * oscale;
                if (OUT_HALF) {
                    *(__half2*)((__half*)Cout + (size_t)r * 1024 + c) =
                        __floats2half2_rn(v0, v1);
                } else {
                    *(float2*)((float*)Cout + (size_t)r * 1024 + c) =
                        make_float2(v0, v1);
                }
            }
        }
    }
}

// QKV projection: blockIdx.z selects Q/K/V (q scaled by QSCALE)
__global__ void __launch_bounds__(256, 1)
qkv_kernel(const float* __restrict__ bq, const float* __restrict__ bk,
           const float* __restrict__ bv, int yoff)
{
    extern __shared__ char smc[];
    const int z = blockIdx.z;
    const __half* W = g_wh + (size_t)z * 1048576;
    const float* b  = (z == 0) ? bq : (z == 1) ? bk : bv;
    __half* O       = (z == 0) ? g_qh : (z == 1) ? g_kh : g_vh;
    const float sc  = (z == 0) ? QSCALE : 1.f;
    hgemm256<1>(g_xh, W, b, O, sc, smc, yoff);
}

// Output projection: out = z @ WoT^T + b_O (float out)
__global__ void __launch_bounds__(256, 1)
out_kernel(const float* __restrict__ bo, float* __restrict__ out, int yoff)
{
    extern __shared__ char smc[];
    hgemm256<0>(g_zh, g_woth, bo, out, 1.f, smc, yoff);
}

// ---------------------------------------------------------------------------
// FP16 tensor-core flash attention, BKEY=128 (empirical optimum: fp16 S
// accumulators, staged fragment arrays for ILP, branch-free mainloop,
// 1 CTA/SM).
// ---------------------------------------------------------------------------
#define FL_SMEM (16384 + 32768 + 32768)   /* Q + K(2x16K) + V(2x16K) = 80KB */

__global__ void __launch_bounds__(256, 1)
flash_kernel(int bb)
{
    extern __shared__ __align__(16) char smc[];
    const uint32_t sQ = (uint32_t)__cvta_generic_to_shared(smc);
    const uint32_t sK = sQ + 16384;
    const uint32_t sV = sK + 32768;

    const int qt  = 15 - blockIdx.x;  // heavy CTAs first
    const int h   = blockIdx.y;
    const int tid = threadIdx.x;
    const int lane = tid & 31;
    const int wid  = tid >> 5;
    const int lane7 = lane & 7;

    const int qbase = qt * 128;
    const int wrow  = wid * 16;
    const size_t base = (size_t)bb * S_ * 1024 + (size_t)h * 64;
    const __half* const Qg = g_qh + base;
    const __half* const Kg = g_kh + base;
    const __half* const Vg = g_vh + base;

    // ---- stage Q (128 rows) ----
#pragma unroll
    for (int i = 0; i < 4; ++i) {
        const int cid = tid + i * 256;          // 0..1023
        const int row = cid >> 3;
        const int kc  = cid & 7;
        const __half* src = Qg + (size_t)(qbase + row) * 1024 + kc * 8;
        const uint32_t dst = sQ + (row << 7) + ((kc ^ (row & 7)) << 4);
        asm volatile("cp.async.cg.shared.global [%0], [%1], 16;\n" :: "r"(dst), "l"(src));
    }
    // ---- stage K/V tile 0 (128 keys) ----
#pragma unroll
    for (int i = 0; i < 8; ++i) {
        const int cid = tid + i * 256;          // 0..2047 : 1024 K, 1024 V
        const int row = (cid >> 3) & 127;
        const int kc  = cid & 7;
        const __half* src = ((cid < 1024) ? Kg : Vg) + (size_t)row * 1024 + kc * 8;
        const uint32_t dst = ((cid < 1024) ? sK : sV)
                           + (row << 7) + ((kc ^ (row & 7)) << 4);
        asm volatile("cp.async.cg.shared.global [%0], [%1], 16;\n" :: "r"(dst), "l"(src));
    }
    asm volatile("cp.async.commit_group;\n");

    // per-thread ldmatrix selectors
    const int qRow    = wrow + (lane & 15);
    const int qCsel   = lane >> 4;
    const int kRowSel = ((lane >> 4) << 3) + lane7;   // + p*16
    const int kPar    = (lane >> 3) & 1;
    const int vRow    = lane & 15;                    // + kt16*16
    const int vCsel   = lane >> 4;                    // + 2*p

    uint32_t qa[4][4];
    float oacc[8][4] = {};
    float l0 = 0.f, l1 = 0.f;
    float mrow0 = -1e30f, mrow1 = -1e30f;

    const int ntile = qt + 1;
    for (int kt = 0; kt < ntile; ++kt) {
        __syncthreads();  // buffer-reuse guard
        if (kt + 1 < ntile) {
            const int kb2 = (kt + 1) * 128;
            const uint32_t boff = ((kt + 1) & 1) * 16384;
#pragma unroll
            for (int i = 0; i < 8; ++i) {
                const int cid = tid + i * 256;
                const int row = (cid >> 3) & 127;
                const int kc  = cid & 7;
                const __half* src = ((cid < 1024) ? Kg : Vg)
                                  + (size_t)(kb2 + row) * 1024 + kc * 8;
                const uint32_t dst = ((cid < 1024) ? sK : sV) + boff
                                   + (row << 7) + ((kc ^ (row & 7)) << 4);
                asm volatile("cp.async.cg.shared.global [%0], [%1], 16;\n" :: "r"(dst), "l"(src));
            }
        }
        asm volatile("cp.async.commit_group;\n");
        asm volatile("cp.async.wait_group 1;\n");
        __syncthreads();

        if (kt == 0) {   // extract Q fragments once (group 0 complete)
#pragma unroll
            for (int kk = 0; kk < 4; ++kk) {
                const uint32_t addr = sQ + (qRow << 7)
                    + ((((kk << 1) + qCsel) ^ (qRow & 7)) << 4);
                ldsm4(qa[kk], addr);
            }
        }

        const uint32_t Kbuf = sK + (kt & 1) * 16384;
        const uint32_t Vbuf = sV + (kt & 1) * 16384;
        const int kbase = kt * 128;

        // ---- S = Q K^T (fp16 accumulators; 16 n-tiles of 8 keys) ----
        uint32_t sacc[16][2] = {};
#pragma unroll
        for (int kk = 0; kk < 4; ++kk) {
            uint32_t bk[16][2];
#pragma unroll
            for (int p = 0; p < 8; ++p) {
                const int row = p * 16 + kRowSel;
                const uint32_t addr = Kbuf + (row << 7)
                    + ((((kk << 1) + kPar) ^ lane7) << 4);
                uint32_t t[4];
                ldsm4(t, addr);
                bk[2 * p][0] = t[0]; bk[2 * p][1] = t[1];
                bk[2 * p + 1][0] = t[2]; bk[2 * p + 1][1] = t[3];
            }
#pragma unroll
            for (int nt = 0; nt < 16; ++nt)
                mma16816h(sacc[nt], qa[kk], bk[nt][0], bk[nt][1]);
        }

        // ---- causal mask (diagonal tile only: kt == qt); -65504h = 0xFBFF ----
        if (kt == qt) {
            const int r0g = qbase + wrow + (lane >> 2);
#pragma unroll
            for (int nt = 0; nt < 16; ++nt) {
                const int cg = kbase + nt * 8 + 2 * (lane & 3);
                {
                    uint32_t s = sacc[nt][0];
                    if (cg + 1 > r0g) s = (s & 0x0000FFFFu) | 0xFBFF0000u;
                    if (cg     > r0g) s = (s & 0xFFFF0000u) | 0x0000FBFFu;
                    sacc[nt][0] = s;
                }
                {
                    uint32_t s = sacc[nt][1];
                    if (cg + 1 > r0g + 8) s = (s & 0x0000FFFFu) | 0xFBFF0000u;
                    if (cg     > r0g + 8) s = (s & 0xFFFF0000u) | 0x0000FBFFu;
                    sacc[nt][1] = s;
                }
            }
        }

        // ---- online softmax (fp16 max chain; maxes fp16-exact) ----
        __half2 hm0 = *(const __half2*)&sacc[0][0];
        __half2 hm1 = *(const __half2*)&sacc[0][1];
#pragma unroll
        for (int nt = 1; nt < 16; ++nt) {
            hm0 = __hmax2(hm0, *(const __half2*)&sacc[nt][0]);
            hm1 = __hmax2(hm1, *(const __half2*)&sacc[nt][1]);
        }
        const float2 fm0 = __half22float2(hm0);
        const float2 fm1 = __half22float2(hm1);
        float mx0 = fmaxf(fm0.x, fm0.y);
        float mx1 = fmaxf(fm1.x, fm1.y);
        mx0 = fmaxf(mx0, __shfl_xor_sync(0xffffffffu, mx0, 1));
        mx0 = fmaxf(mx0, __shfl_xor_sync(0xffffffffu, mx0, 2));
        mx1 = fmaxf(mx1, __shfl_xor_sync(0xffffffffu, mx1, 1));
        mx1 = fmaxf(mx1, __shfl_xor_sync(0xffffffffu, mx1, 2));

        const float mn0 = fmaxf(mrow0, mx0);
        const float mn1 = fmaxf(mrow1, mx1);
        const float alpha0 = ex2f(mrow0 - mn0);
        const float alpha1 = ex2f(mrow1 - mn1);
        mrow0 = mn0; mrow1 = mn1;

        const __half2 mh0 = __float2half2_rn(mn0);   // exact
        const __half2 mh1 = __float2half2_rn(mn1);

        uint32_t ph[16][2];
#pragma unroll
        for (int nt = 0; nt < 16; ++nt) {
            const __half2 d0 = __hsub2(*(const __half2*)&sacc[nt][0], mh0);
            const __half2 d1 = __hsub2(*(const __half2*)&sacc[nt][1], mh1);
            ph[nt][0] = h2ex2(*(const uint32_t*)&d0);
            ph[nt][1] = h2ex2(*(const uint32_t*)&d1);
        }

        // ---- row sums on fma/alu pipes ----
        float rs0 = 0.f, rs1 = 0.f;
#pragma unroll
        for (int nt = 0; nt < 16; nt += 2) {
            const __half2 a0 = __hadd2(*(const __half2*)&ph[nt][0],
                                       *(const __half2*)&ph[nt + 1][0]);
            const __half2 a1 = __hadd2(*(const __half2*)&ph[nt][1],
                                       *(const __half2*)&ph[nt + 1][1]);
            const float2 f0 = __half22float2(a0);
            const float2 f1 = __half22float2(a1);
            rs0 += f0.x + f0.y;
            rs1 += f1.x + f1.y;
        }
        rs0 += __shfl_xor_sync(0xffffffffu, rs0, 1);
        rs0 += __shfl_xor_sync(0xffffffffu, rs0, 2);
        rs1 += __shfl_xor_sync(0xffffffffu, rs1, 1);
        rs1 += __shfl_xor_sync(0xffffffffu, rs1, 2);
        l0 = l0 * alpha0 + rs0;
        l1 = l1 * alpha1 + rs1;

#pragma unroll
        for (int nt = 0; nt < 8; ++nt) {
            oacc[nt][0] *= alpha0; oacc[nt][1] *= alpha0;
            oacc[nt][2] *= alpha1; oacc[nt][3] *= alpha1;
        }

        // ---- O += P V (fp32 accumulators) ----
#pragma unroll
        for (int kt16 = 0; kt16 < 8; ++kt16) {
            uint32_t pa[4];
            pa[0] = ph[2 * kt16][0];
            pa[1] = ph[2 * kt16][1];
            pa[2] = ph[2 * kt16 + 1][0];
            pa[3] = ph[2 * kt16 + 1][1];

            uint32_t bv[8][2];
#pragma unroll
            for (int p = 0; p < 4; ++p) {
                const int row = kt16 * 16 + vRow;
                const uint32_t addr = Vbuf + (row << 7)
                    + ((((p << 1) + vCsel) ^ (row & 7)) << 4);
                uint32_t t[4];
                ldsm4t(t, addr);
                bv[2 * p][0] = t[0]; bv[2 * p][1] = t[1];
                bv[2 * p + 1][0] = t[2]; bv[2 * p + 1][1] = t[3];
            }
#pragma unroll
            for (int nt = 0; nt < 8; ++nt)
                mma16816(oacc[nt], pa, bv[nt][0], bv[nt][1]);
        }
    }

    // ---- normalize + write z (half) ----
    const float inv0 = 1.f / l0;
    const float inv1 = 1.f / l1;
    __half* const Zg = g_zh + base;
    const int r0 = qbase + wrow + (lane >> 2);
#pragma unroll
    for (int nt = 0; nt < 8; ++nt) {
        const int c = nt * 8 + 2 * (lane & 3);
        *(__half2*)(Zg + (size_t)r0 * 1024 + c) =
            __floats2half2_rn(oacc[nt][0] * inv0, oacc[nt][1] * inv0);
        *(__half2*)(Zg + (size_t)(r0 + 8) * 1024 + c) =
            __floats2half2_rn(oacc[nt][2] * inv1, oacc[nt][3] * inv1);
    }
}

// ---------------------------------------------------------------------------
extern "C" void kernel_launch(void* const* d_in, const int* in_sizes, int n_in,
                              void* d_out, int out_size)
{
    (void)in_sizes; (void)n_in; (void)out_size;
    const float* x  = (const float*)d_in[0];
    const float* Wq = (const float*)d_in[1];
    const float* Wk = (const float*)d_in[2];
    const float* Wv = (const float*)d_in[3];
    const float* Wo = (const float*)d_in[4];
    const float* bq = (const float*)d_in[5];
    const float* bk = (const float*)d_in[6];
    const float* bv = (const float*)d_in[7];
    const float* bo = (const float*)d_in[8];
    float* out = (float*)d_out;

    cudaFuncSetAttribute(flash_kernel,
                         cudaFuncAttributeMaxDynamicSharedMemorySize, FL_SMEM);
    cudaFuncSetAttribute(qkv_kernel,
                         cudaFuncAttributeMaxDynamicSharedMemorySize, HG_SMEM);
    cudaFuncSetAttribute(out_kernel,
                         cudaFuncAttributeMaxDynamicSharedMemorySize, HG_SMEM);

    cudaStream_t s1, s2;
    cudaStreamCreateWithFlags(&s1, cudaStreamNonBlocking);
    cudaStreamCreateWithFlags(&s2, cudaStreamNonBlocking);
    cudaEvent_t evFork, evPrep, evWO, evJoin;
    cudaEventCreateWithFlags(&evFork, cudaEventDisableTiming);
    cudaEventCreateWithFlags(&evPrep, cudaEventDisableTiming);
    cudaEventCreateWithFlags(&evWO,   cudaEventDisableTiming);
    cudaEventCreateWithFlags(&evJoin, cudaEventDisableTiming);

    // fork s2 for the W_O transpose (only needed by the out_kernels)
    cudaEventRecord(evFork, 0);
    cudaStreamWaitEvent(s2, evFork, 0);
    prep_wo_kernel<<<1024, 256, 0, s2>>>(Wo);
    cudaEventRecord(evWO, s2);

    // critical-path prep (x + W_QKV), then fork s1 for batch 1
    prep_kernel<<<1792, 256>>>(x, Wq, Wk, Wv);
    cudaEventRecord(evPrep, 0);
    cudaStreamWaitEvent(s1, evPrep, 0);

    // chain 0 (rows 0..2047 = batch 0) on the default stream
    qkv_kernel<<<dim3(8, 8, 3), 256, HG_SMEM>>>(bq, bk, bv, 0);
    flash_kernel<<<dim3(16, 16), 256, FL_SMEM>>>(0);
    cudaStreamWaitEvent(0, evWO, 0);
    out_kernel<<<dim3(8, 8), 256, HG_SMEM>>>(bo, out, 0);

    // chain 1 (rows 2048..4095 = batch 1) on s1
    qkv_kernel<<<dim3(8, 8, 3), 256, HG_SMEM, s1>>>(bq, bk, bv, 8);
    flash_kernel<<<dim3(16, 16), 256, FL_SMEM, s1>>>(1);
    cudaStreamWaitEvent(s1, evWO, 0);
    out_kernel<<<dim3(8, 8), 256, HG_SMEM, s1>>>(bo, out, 8);

    cudaEventRecord(evJoin, s1);
    cudaStreamWaitEvent(0, evJoin, 0);

    cudaEventDestroy(evFork);
    cudaEventDestroy(evPrep);
    cudaEventDestroy(evWO);
    cudaEventDestroy(evJoin);
    cudaStreamDestroy(s1);
    cudaStreamDestroy(s2);
}